// round 1
// baseline (speedup 1.0000x reference)
#include <cuda_runtime.h>

#define Hh 50
#define BT 32
#define TPB 256

// Transposed x: xT[t][b], filled by transpose kernel. 8 MB static device buffer.
__device__ float g_xT[512 * 4096];

// -------------------- x transpose: x[b][t] -> xT[t][b] --------------------
__global__ void transpose_kernel(const float* __restrict__ x, int B, int T) {
    __shared__ float tile[32][33];
    int bx = blockIdx.x * 32;  // t offset
    int by = blockIdx.y * 32;  // b offset
    int tx = threadIdx.x, ty = threadIdx.y;
#pragma unroll
    for (int i = 0; i < 32; i += 8)
        tile[ty + i][tx] = x[(size_t)(by + ty + i) * T + (bx + tx)];
    __syncthreads();
#pragma unroll
    for (int i = 0; i < 32; i += 8)
        g_xT[(size_t)(bx + ty + i) * B + (by + tx)] = tile[tx][ty + i];
}

// -------------------- fast nonlinearities --------------------
__device__ __forceinline__ float sigf(float x) {
    return __fdividef(1.f, 1.f + __expf(-x));
}
__device__ __forceinline__ float tanf_(float x) {
    return __fdividef(2.f, 1.f + __expf(-2.f * x)) - 1.f;
}

// smem layout (floats):
//  W1s: 50*50*4  = 10000   @ 0       W1s[((k*50)+kp)*4+g] = W_hh0[(g*50+k)*50+kp]
//  W2s: 50*100*4 = 20000   @ 10000   kp<50 -> W_ih1 row, kp>=50 -> W_hh1 row
//  wx1: 200                @ 30000
//  bs1: 200                @ 30200
//  bs2: 200                @ 30400
//  hc : 100*32   = 3200    @ 30600   hc[k'][b]; rows 0..49 = h1, 50..99 = h2
#define SME_TOT 33800

__global__ __launch_bounds__(TPB) void lstm_kernel(
    const float* __restrict__ W_ih0, const float* __restrict__ W_hh0,
    const float* __restrict__ b_ih0, const float* __restrict__ b_hh0,
    const float* __restrict__ W_ih1, const float* __restrict__ W_hh1,
    const float* __restrict__ b_ih1, const float* __restrict__ b_hh1,
    const float* __restrict__ W_fc, const float* __restrict__ b_fc,
    float* __restrict__ out, int B, int T)
{
    extern __shared__ float sm[];
    float* W1s = sm;
    float* W2s = sm + 10000;
    float* wx1 = sm + 30000;
    float* bs1 = sm + 30200;
    float* bs2 = sm + 30400;
    float* hc  = sm + 30600;

    const int tid = threadIdx.x;

    // ---- pack weights into smem ----
    for (int i = tid; i < 10000; i += TPB) {
        int g = i & 3; int kp = (i >> 2) % Hh; int k = i / (Hh * 4);
        W1s[i] = W_hh0[(g * Hh + k) * Hh + kp];
    }
    for (int i = tid; i < 20000; i += TPB) {
        int g = i & 3; int kp = (i >> 2) % 100; int k = i / 400;
        W2s[i] = (kp < Hh) ? W_ih1[(g * Hh + k) * Hh + kp]
                           : W_hh1[(g * Hh + k) * Hh + (kp - Hh)];
    }
    for (int i = tid; i < 200; i += TPB) {
        int g = i & 3; int k = i >> 2;
        wx1[i] = W_ih0[g * Hh + k];
        bs1[i] = b_ih0[g * Hh + k] + b_hh0[g * Hh + k];
        bs2[i] = b_ih1[g * Hh + k] + b_hh1[g * Hh + k];
    }
    for (int i = tid; i < 100 * BT; i += TPB) hc[i] = 0.f;

    const int w = tid >> 5;      // warp 0..7 -> base hidden index
    const int b = tid & 31;      // batch lane within tile
    const int bbase = blockIdx.x * BT;

    // hidden units owned by this thread: k = w + 8*s, s = 0..(nslots-1)
    // warps 0,1: 7 slots; warps 2..7: 6 slots. Pairs (0,1)(2,3)(4,5), single s=6.
    const bool has7 = (w < 2);

    float c1v[7], c2v[7], nh1[7], nh2[7];
#pragma unroll
    for (int s = 0; s < 7; s++) { c1v[s] = 0.f; c2v[s] = 0.f; nh1[s] = 0.f; nh2[s] = 0.f; }

    __syncthreads();

    for (int t = 0; t < T; t++) {
        const float xv = g_xT[(size_t)t * B + bbase + b];

        // ---------------- phase A: layer 1 (reads hc[0..50) = h1 old) ----------------
#pragma unroll
        for (int s = 0; s < 6; s += 2) {
            const int k0 = w + (s << 3);
            const int k1 = k0 + 8;
            float a0, a1, a2, a3, a4, a5, a6, a7;
            {
                float4 bb = *(const float4*)(bs1 + k0 * 4);
                float4 wx = *(const float4*)(wx1 + k0 * 4);
                a0 = fmaf(xv, wx.x, bb.x); a1 = fmaf(xv, wx.y, bb.y);
                a2 = fmaf(xv, wx.z, bb.z); a3 = fmaf(xv, wx.w, bb.w);
            }
            {
                float4 bb = *(const float4*)(bs1 + k1 * 4);
                float4 wx = *(const float4*)(wx1 + k1 * 4);
                a4 = fmaf(xv, wx.x, bb.x); a5 = fmaf(xv, wx.y, bb.y);
                a6 = fmaf(xv, wx.z, bb.z); a7 = fmaf(xv, wx.w, bb.w);
            }
            const float4* w0p = (const float4*)(W1s + k0 * Hh * 4);
            const float4* w1p = (const float4*)(W1s + k1 * Hh * 4);
#pragma unroll 10
            for (int kp = 0; kp < Hh; kp++) {
                float h = hc[kp * BT + b];
                float4 w0 = w0p[kp];
                float4 w1 = w1p[kp];
                a0 = fmaf(w0.x, h, a0); a1 = fmaf(w0.y, h, a1);
                a2 = fmaf(w0.z, h, a2); a3 = fmaf(w0.w, h, a3);
                a4 = fmaf(w1.x, h, a4); a5 = fmaf(w1.y, h, a5);
                a6 = fmaf(w1.z, h, a6); a7 = fmaf(w1.w, h, a7);
            }
            float c0 = sigf(a1) * c1v[s] + sigf(a0) * tanf_(a2);
            c1v[s] = c0;
            nh1[s] = sigf(a3) * tanf_(c0);
            float c1 = sigf(a5) * c1v[s + 1] + sigf(a4) * tanf_(a6);
            c1v[s + 1] = c1;
            nh1[s + 1] = sigf(a7) * tanf_(c1);
        }
        if (has7) {
            const int k0 = w + 48;
            float a0, a1, a2, a3;
            float4 bb = *(const float4*)(bs1 + k0 * 4);
            float4 wx = *(const float4*)(wx1 + k0 * 4);
            a0 = fmaf(xv, wx.x, bb.x); a1 = fmaf(xv, wx.y, bb.y);
            a2 = fmaf(xv, wx.z, bb.z); a3 = fmaf(xv, wx.w, bb.w);
            const float4* w0p = (const float4*)(W1s + k0 * Hh * 4);
#pragma unroll 10
            for (int kp = 0; kp < Hh; kp++) {
                float h = hc[kp * BT + b];
                float4 w0 = w0p[kp];
                a0 = fmaf(w0.x, h, a0); a1 = fmaf(w0.y, h, a1);
                a2 = fmaf(w0.z, h, a2); a3 = fmaf(w0.w, h, a3);
            }
            float c0 = sigf(a1) * c1v[6] + sigf(a0) * tanf_(a2);
            c1v[6] = c0;
            nh1[6] = sigf(a3) * tanf_(c0);
        }

        __syncthreads();   // all reads of old h1 done
#pragma unroll
        for (int s = 0; s < 6; s++) hc[(w + (s << 3)) * BT + b] = nh1[s];
        if (has7) hc[(w + 48) * BT + b] = nh1[6];
        __syncthreads();   // new h1 visible

        // ---------------- phase B: layer 2 (reads hc[0..100): h1 new, h2 old) --------
#pragma unroll
        for (int s = 0; s < 6; s += 2) {
            const int k0 = w + (s << 3);
            const int k1 = k0 + 8;
            float a0, a1, a2, a3, a4, a5, a6, a7;
            {
                float4 bb = *(const float4*)(bs2 + k0 * 4);
                a0 = bb.x; a1 = bb.y; a2 = bb.z; a3 = bb.w;
            }
            {
                float4 bb = *(const float4*)(bs2 + k1 * 4);
                a4 = bb.x; a5 = bb.y; a6 = bb.z; a7 = bb.w;
            }
            const float4* w0p = (const float4*)(W2s + k0 * 100 * 4);
            const float4* w1p = (const float4*)(W2s + k1 * 100 * 4);
#pragma unroll 10
            for (int kp = 0; kp < 100; kp++) {
                float h = hc[kp * BT + b];
                float4 w0 = w0p[kp];
                float4 w1 = w1p[kp];
                a0 = fmaf(w0.x, h, a0); a1 = fmaf(w0.y, h, a1);
                a2 = fmaf(w0.z, h, a2); a3 = fmaf(w0.w, h, a3);
                a4 = fmaf(w1.x, h, a4); a5 = fmaf(w1.y, h, a5);
                a6 = fmaf(w1.z, h, a6); a7 = fmaf(w1.w, h, a7);
            }
            float c0 = sigf(a1) * c2v[s] + sigf(a0) * tanf_(a2);
            c2v[s] = c0;
            nh2[s] = sigf(a3) * tanf_(c0);
            float c1 = sigf(a5) * c2v[s + 1] + sigf(a4) * tanf_(a6);
            c2v[s + 1] = c1;
            nh2[s + 1] = sigf(a7) * tanf_(c1);
        }
        if (has7) {
            const int k0 = w + 48;
            float a0, a1, a2, a3;
            float4 bb = *(const float4*)(bs2 + k0 * 4);
            a0 = bb.x; a1 = bb.y; a2 = bb.z; a3 = bb.w;
            const float4* w0p = (const float4*)(W2s + k0 * 100 * 4);
#pragma unroll 10
            for (int kp = 0; kp < 100; kp++) {
                float h = hc[kp * BT + b];
                float4 w0 = w0p[kp];
                a0 = fmaf(w0.x, h, a0); a1 = fmaf(w0.y, h, a1);
                a2 = fmaf(w0.z, h, a2); a3 = fmaf(w0.w, h, a3);
            }
            float c0 = sigf(a1) * c2v[6] + sigf(a0) * tanf_(a2);
            c2v[6] = c0;
            nh2[6] = sigf(a3) * tanf_(c0);
        }

        __syncthreads();   // all reads of old h2 done
#pragma unroll
        for (int s = 0; s < 6; s++) hc[(Hh + w + (s << 3)) * BT + b] = nh2[s];
        if (has7) hc[(Hh + w + 48) * BT + b] = nh2[6];
        // no sync needed here: next phase A only touches hc[0..50); ordering
        // to next phase B is provided by the two barriers above.
    }

    __syncthreads();
    // ---- final FC: out[b] = h2_last[b] . W_fc + b_fc ----
    if (tid < BT) {
        float acc = b_fc[0];
#pragma unroll 10
        for (int k = 0; k < Hh; k++)
            acc = fmaf(hc[(Hh + k) * BT + tid], W_fc[k], acc);
        out[bbase + tid] = acc;
    }
}

extern "C" void kernel_launch(void* const* d_in, const int* in_sizes, int n_in,
                              void* d_out, int out_size) {
    const float* x     = (const float*)d_in[0];
    const float* W_ih0 = (const float*)d_in[1];
    const float* W_hh0 = (const float*)d_in[2];
    const float* b_ih0 = (const float*)d_in[3];
    const float* b_hh0 = (const float*)d_in[4];
    const float* W_ih1 = (const float*)d_in[5];
    const float* W_hh1 = (const float*)d_in[6];
    const float* b_ih1 = (const float*)d_in[7];
    const float* b_hh1 = (const float*)d_in[8];
    const float* W_fc  = (const float*)d_in[9];
    const float* b_fc  = (const float*)d_in[10];
    float* out = (float*)d_out;

    int B = out_size;                 // 4096
    int T = in_sizes[0] / B;          // 512

    dim3 tb(32, 8), tg(T / 32, B / 32);
    transpose_kernel<<<tg, tb>>>(x, B, T);

    cudaFuncSetAttribute(lstm_kernel, cudaFuncAttributeMaxDynamicSharedMemorySize,
                         SME_TOT * sizeof(float));
    lstm_kernel<<<B / BT, TPB, SME_TOT * sizeof(float)>>>(
        W_ih0, W_hh0, b_ih0, b_hh0, W_ih1, W_hh1, b_ih1, b_hh1,
        W_fc, b_fc, out, B, T);
}

// round 5
// speedup vs baseline: 1.6666x; 1.6666x over previous
#include <cuda_runtime.h>

#define BT 32
#define TPB 800
#define NW 25

// Transposed x: xT[t][b]. 8 MB static device buffer.
__device__ float g_xT[512 * 4096];

__global__ void transpose_kernel(const float* __restrict__ x, int B, int T) {
    __shared__ float tile[32][33];
    int bx = blockIdx.x * 32;  // t offset
    int by = blockIdx.y * 32;  // b offset
    int tx = threadIdx.x, ty = threadIdx.y;
#pragma unroll
    for (int i = 0; i < 32; i += 8)
        tile[ty + i][tx] = x[(size_t)(by + ty + i) * T + (bx + tx)];
    __syncthreads();
#pragma unroll
    for (int i = 0; i < 32; i += 8)
        g_xT[(size_t)(bx + ty + i) * B + (by + tx)] = tile[tx][ty + i];
}

// -------------------- f32x2 helpers (sm_103a FFMA2) --------------------
__device__ __forceinline__ unsigned long long pack2(float a, float b) {
    unsigned long long r;
    asm("mov.b64 %0, {%1, %2};" : "=l"(r)
        : "r"(__float_as_uint(a)), "r"(__float_as_uint(b)));
    return r;
}
__device__ __forceinline__ float2 unpack2(unsigned long long v) {
    unsigned lo, hi;
    asm("mov.b64 {%0, %1}, %2;" : "=r"(lo), "=r"(hi) : "l"(v));
    return make_float2(__uint_as_float(lo), __uint_as_float(hi));
}
__device__ __forceinline__ void ffma2(unsigned long long& d,
                                      unsigned long long a,
                                      unsigned long long b) {
    asm("fma.rn.f32x2 %0, %1, %2, %0;" : "+l"(d) : "l"(a), "l"(b));
}

__device__ __forceinline__ float sigf(float x) {
    return __fdividef(1.f, 1.f + __expf(-x));
}
__device__ __forceinline__ float tanf_(float x) {
    return __fdividef(2.f, 1.f + __expf(-2.f * x)) - 1.f;
}

// smem layout (floats):
//  W1q: 50k * 4g * 52kp = 10400 @ 0      W1q[(k*4+g)*52+kp] = W_hh0[g*50+k][kp] (kp>=50 -> 0)
//  W2q: 50k * 4g * 104kp= 20800 @ 10400  kp<50: W_ih1 row; 50<=kp<100: W_hh1; else 0
//  wx1: 200  @ 31200   [k][4] gate-packed
//  bs1: 200  @ 31400
//  bs2: 200  @ 31600
//  hcT: 32*100 + 16 slack = 3216 @ 31800   hcT[b*100 + kp]; 0..49 h1, 50..99 h2
#define SME_TOT 35016

__global__ __launch_bounds__(TPB, 1) void lstm_kernel(
    const float* __restrict__ W_ih0, const float* __restrict__ W_hh0,
    const float* __restrict__ b_ih0, const float* __restrict__ b_hh0,
    const float* __restrict__ W_ih1, const float* __restrict__ W_hh1,
    const float* __restrict__ b_ih1, const float* __restrict__ b_hh1,
    const float* __restrict__ W_fc, const float* __restrict__ b_fc,
    float* __restrict__ out, int B, int T)
{
    extern __shared__ float sm[];
    float* W1q = sm;
    float* W2q = sm + 10400;
    float* wx1 = sm + 31200;
    float* bs1 = sm + 31400;
    float* bs2 = sm + 31600;
    float* hcT = sm + 31800;

    const int tid = threadIdx.x;

    // ---- pack weights ----
    for (int i = tid; i < 10400; i += TPB) {
        int k = i / 208, r = i % 208, g = r / 52, kp = r % 52;
        W1q[i] = (kp < 50) ? W_hh0[(g * 50 + k) * 50 + kp] : 0.f;
    }
    for (int i = tid; i < 20800; i += TPB) {
        int k = i / 416, r = i % 416, g = r / 104, kp = r % 104;
        float v = 0.f;
        if (kp < 50)       v = W_ih1[(g * 50 + k) * 50 + kp];
        else if (kp < 100) v = W_hh1[(g * 50 + k) * 50 + (kp - 50)];
        W2q[i] = v;
    }
    for (int i = tid; i < 200; i += TPB) {
        int g = i & 3, k = i >> 2;
        wx1[i] = W_ih0[g * 50 + k];
        bs1[i] = b_ih0[g * 50 + k] + b_hh0[g * 50 + k];
        bs2[i] = b_ih1[g * 50 + k] + b_hh1[g * 50 + k];
    }
    for (int i = tid; i < 3216; i += TPB) hcT[i] = 0.f;

    const int w = tid >> 5;       // warp 0..24
    const int b = tid & 31;       // batch lane
    const int bbase = blockIdx.x * BT;
    const int k0 = w, k1 = w + 25;

    float c10 = 0.f, c11 = 0.f, c20 = 0.f, c21 = 0.f;

    const ulonglong2* hPu = (const ulonglong2*)(hcT + b * 100);
    const ulonglong2* B10 = (const ulonglong2*)(W1q + k0 * 208);  // 13 u64x2 per gate row
    const ulonglong2* B11 = (const ulonglong2*)(W1q + k1 * 208);
    const ulonglong2* B20 = (const ulonglong2*)(W2q + k0 * 416);  // 26 u64x2 per gate row
    const ulonglong2* B21 = (const ulonglong2*)(W2q + k1 * 416);

    __syncthreads();

    for (int t = 0; t < T; t++) {
        const float xv = g_xT[(size_t)t * B + bbase + b];

        // ================= layer 1: kp = 0..51 (50,51 hit h2[0..1] * zero w) =================
        unsigned long long a00, a01, a02, a03, a10, a11, a12, a13;
        {
            float4 bb = *(const float4*)(bs1 + k0 * 4);
            float4 wx = *(const float4*)(wx1 + k0 * 4);
            a00 = pack2(fmaf(xv, wx.x, bb.x), 0.f);
            a01 = pack2(fmaf(xv, wx.y, bb.y), 0.f);
            a02 = pack2(fmaf(xv, wx.z, bb.z), 0.f);
            a03 = pack2(fmaf(xv, wx.w, bb.w), 0.f);
        }
        {
            float4 bb = *(const float4*)(bs1 + k1 * 4);
            float4 wx = *(const float4*)(wx1 + k1 * 4);
            a10 = pack2(fmaf(xv, wx.x, bb.x), 0.f);
            a11 = pack2(fmaf(xv, wx.y, bb.y), 0.f);
            a12 = pack2(fmaf(xv, wx.z, bb.z), 0.f);
            a13 = pack2(fmaf(xv, wx.w, bb.w), 0.f);
        }
#pragma unroll
        for (int j = 0; j < 13; j++) {
            ulonglong2 hu = hPu[j];   // h[4j..4j+3] as 2 packed pairs
            { ulonglong2 t0 = B10[j];      ffma2(a00, t0.x, hu.x); ffma2(a00, t0.y, hu.y); }
            { ulonglong2 t0 = B10[13 + j]; ffma2(a01, t0.x, hu.x); ffma2(a01, t0.y, hu.y); }
            { ulonglong2 t0 = B10[26 + j]; ffma2(a02, t0.x, hu.x); ffma2(a02, t0.y, hu.y); }
            { ulonglong2 t0 = B10[39 + j]; ffma2(a03, t0.x, hu.x); ffma2(a03, t0.y, hu.y); }
            { ulonglong2 t0 = B11[j];      ffma2(a10, t0.x, hu.x); ffma2(a10, t0.y, hu.y); }
            { ulonglong2 t0 = B11[13 + j]; ffma2(a11, t0.x, hu.x); ffma2(a11, t0.y, hu.y); }
            { ulonglong2 t0 = B11[26 + j]; ffma2(a12, t0.x, hu.x); ffma2(a12, t0.y, hu.y); }
            { ulonglong2 t0 = B11[39 + j]; ffma2(a13, t0.x, hu.x); ffma2(a13, t0.y, hu.y); }
        }
        float nh0, nh1;
        {
            float2 vi = unpack2(a00), vf = unpack2(a01), vg = unpack2(a02), vo = unpack2(a03);
            float gi = vi.x + vi.y, gf = vf.x + vf.y, gg = vg.x + vg.y, go = vo.x + vo.y;
            c10 = sigf(gf) * c10 + sigf(gi) * tanf_(gg);
            nh0 = sigf(go) * tanf_(c10);
        }
        {
            float2 vi = unpack2(a10), vf = unpack2(a11), vg = unpack2(a12), vo = unpack2(a13);
            float gi = vi.x + vi.y, gf = vf.x + vf.y, gg = vg.x + vg.y, go = vo.x + vo.y;
            c11 = sigf(gf) * c11 + sigf(gi) * tanf_(gg);
            nh1 = sigf(go) * tanf_(c11);
        }

        __syncthreads();   // all reads of old h1 done
        hcT[b * 100 + k0] = nh0;
        hcT[b * 100 + k1] = nh1;
        __syncthreads();   // new h1 visible

        // ================= layer 2: kp = 0..103 (100..103 hit slack/next row * zero w) =====
        {
            float4 bb = *(const float4*)(bs2 + k0 * 4);
            a00 = pack2(bb.x, 0.f); a01 = pack2(bb.y, 0.f);
            a02 = pack2(bb.z, 0.f); a03 = pack2(bb.w, 0.f);
        }
        {
            float4 bb = *(const float4*)(bs2 + k1 * 4);
            a10 = pack2(bb.x, 0.f); a11 = pack2(bb.y, 0.f);
            a12 = pack2(bb.z, 0.f); a13 = pack2(bb.w, 0.f);
        }
#pragma unroll
        for (int j = 0; j < 26; j++) {
            ulonglong2 hu = hPu[j];
            { ulonglong2 t0 = B20[j];      ffma2(a00, t0.x, hu.x); ffma2(a00, t0.y, hu.y); }
            { ulonglong2 t0 = B20[26 + j]; ffma2(a01, t0.x, hu.x); ffma2(a01, t0.y, hu.y); }
            { ulonglong2 t0 = B20[52 + j]; ffma2(a02, t0.x, hu.x); ffma2(a02, t0.y, hu.y); }
            { ulonglong2 t0 = B20[78 + j]; ffma2(a03, t0.x, hu.x); ffma2(a03, t0.y, hu.y); }
            { ulonglong2 t0 = B21[j];      ffma2(a10, t0.x, hu.x); ffma2(a10, t0.y, hu.y); }
            { ulonglong2 t0 = B21[26 + j]; ffma2(a11, t0.x, hu.x); ffma2(a11, t0.y, hu.y); }
            { ulonglong2 t0 = B21[52 + j]; ffma2(a12, t0.x, hu.x); ffma2(a12, t0.y, hu.y); }
            { ulonglong2 t0 = B21[78 + j]; ffma2(a13, t0.x, hu.x); ffma2(a13, t0.y, hu.y); }
        }
        {
            float2 vi = unpack2(a00), vf = unpack2(a01), vg = unpack2(a02), vo = unpack2(a03);
            float gi = vi.x + vi.y, gf = vf.x + vf.y, gg = vg.x + vg.y, go = vo.x + vo.y;
            c20 = sigf(gf) * c20 + sigf(gi) * tanf_(gg);
            nh0 = sigf(go) * tanf_(c20);
        }
        {
            float2 vi = unpack2(a10), vf = unpack2(a11), vg = unpack2(a12), vo = unpack2(a13);
            float gi = vi.x + vi.y, gf = vf.x + vf.y, gg = vg.x + vg.y, go = vo.x + vo.y;
            c21 = sigf(gf) * c21 + sigf(gi) * tanf_(gg);
            nh1 = sigf(go) * tanf_(c21);
        }

        __syncthreads();   // all reads of old h2 done
        hcT[b * 100 + 50 + k0] = nh0;
        hcT[b * 100 + 50 + k1] = nh1;
        // next phase A reads rows 0..51; rows 50..51 race benignly (finite * zero weight),
        // phase B ordering is covered by the two barriers of the next step.
    }

    __syncthreads();
    // ---- final FC ----
    if (tid < BT) {
        float acc = b_fc[0];
#pragma unroll 10
        for (int k = 0; k < 50; k++)
            acc = fmaf(hcT[tid * 100 + 50 + k], W_fc[k], acc);
        out[bbase + tid] = acc;
    }
}

extern "C" void kernel_launch(void* const* d_in, const int* in_sizes, int n_in,
                              void* d_out, int out_size) {
    const float* x     = (const float*)d_in[0];
    const float* W_ih0 = (const float*)d_in[1];
    const float* W_hh0 = (const float*)d_in[2];
    const float* b_ih0 = (const float*)d_in[3];
    const float* b_hh0 = (const float*)d_in[4];
    const float* W_ih1 = (const float*)d_in[5];
    const float* W_hh1 = (const float*)d_in[6];
    const float* b_ih1 = (const float*)d_in[7];
    const float* b_hh1 = (const float*)d_in[8];
    const float* W_fc  = (const float*)d_in[9];
    const float* b_fc  = (const float*)d_in[10];
    float* out = (float*)d_out;

    int B = out_size;                 // 4096
    int T = in_sizes[0] / B;          // 512

    dim3 tb(32, 8), tg(T / 32, B / 32);
    transpose_kernel<<<tg, tb>>>(x, B, T);

    cudaFuncSetAttribute(lstm_kernel, cudaFuncAttributeMaxDynamicSharedMemorySize,
                         SME_TOT * sizeof(float));
    lstm_kernel<<<B / BT, TPB, SME_TOT * sizeof(float)>>>(
        W_ih0, W_hh0, b_ih0, b_hh0, W_ih1, W_hh1, b_ih1, b_hh1,
        W_fc, b_fc, out, B, T);
}

// round 6
// speedup vs baseline: 2.1244x; 1.2747x over previous
#include <cuda_runtime.h>

#define BT 32
#define TPB 416     // 13 warps: warp = k-group (4 k each, 52 padded)
#define NW 13

// Transposed x: xT[t][b]. 8 MB static device buffer.
__device__ float g_xT[512 * 4096];

__global__ void transpose_kernel(const float* __restrict__ x, int B, int T) {
    __shared__ float tile[32][33];
    int bx = blockIdx.x * 32;  // t offset
    int by = blockIdx.y * 32;  // b offset
    int tx = threadIdx.x, ty = threadIdx.y;
#pragma unroll
    for (int i = 0; i < 32; i += 8)
        tile[ty + i][tx] = x[(size_t)(by + ty + i) * T + (bx + tx)];
    __syncthreads();
#pragma unroll
    for (int i = 0; i < 32; i += 8)
        g_xT[(size_t)(bx + ty + i) * B + (by + tx)] = tile[tx][ty + i];
}

// -------------------- f32x2 helpers (sm_103a FFMA2) --------------------
typedef unsigned long long ull;
__device__ __forceinline__ ull pack2(float a, float b) {
    ull r;
    asm("mov.b64 %0, {%1, %2};" : "=l"(r)
        : "r"(__float_as_uint(a)), "r"(__float_as_uint(b)));
    return r;
}
__device__ __forceinline__ float2 unpack2(ull v) {
    unsigned lo, hi;
    asm("mov.b64 {%0, %1}, %2;" : "=r"(lo), "=r"(hi) : "l"(v));
    return make_float2(__uint_as_float(lo), __uint_as_float(hi));
}
__device__ __forceinline__ void ffma2(ull& d, ull a, ull b) {
    asm("fma.rn.f32x2 %0, %1, %2, %0;" : "+l"(d) : "l"(a), "l"(b));
}

__device__ __forceinline__ float sigf(float x) {
    return __fdividef(1.f, 1.f + __expf(-x));
}
__device__ __forceinline__ float tanf_(float x) {
    return __fdividef(2.f, 1.f + __expf(-2.f * x)) - 1.f;
}

// smem layout (floats):
//  W1n: 13kg*13j*4g*(4k_id*4c) = 10816 @ 0
//       16B chunk @ [((kg*13+j)*4+g)*16 + k_id*4] = W_hh0[g*50+k][4j..4j+3], k=kg*4+k_id
//       (zero if k>=50 or kp>=50)
//  W2n: 13kg*26j*4g*16 = 21632 @ 10816   kp<50: W_ih1; 50..99: W_hh1; else 0
//  wx1n/bs1n/bs2n: [kg][k_id][g] float4, 208 each @ 32448/32656/32864
//  hcT: 32*100 + 16 slack = 3216 @ 33072  hcT[b*100+kp]; 0..49 h1, 50..99 h2
#define SME_TOT 36288

__global__ __launch_bounds__(TPB, 1) void lstm_kernel(
    const float* __restrict__ W_ih0, const float* __restrict__ W_hh0,
    const float* __restrict__ b_ih0, const float* __restrict__ b_hh0,
    const float* __restrict__ W_ih1, const float* __restrict__ W_hh1,
    const float* __restrict__ b_ih1, const float* __restrict__ b_hh1,
    const float* __restrict__ W_fc, const float* __restrict__ b_fc,
    float* __restrict__ out, int B, int T)
{
    extern __shared__ float sm[];
    float* W1n  = sm;
    float* W2n  = sm + 10816;
    float* wx1n = sm + 32448;
    float* bs1n = sm + 32656;
    float* bs2n = sm + 32864;
    float* hcT  = sm + 33072;

    const int tid = threadIdx.x;

    // ---- pack weights ----
    for (int i = tid; i < 10816; i += TPB) {
        int kg = i / 832, r = i % 832;
        int j = r / 64, g = (r % 64) / 16, k_id = (r % 16) / 4, c = r % 4;
        int k = kg * 4 + k_id, kp = j * 4 + c;
        W1n[i] = (k < 50 && kp < 50) ? W_hh0[(g * 50 + k) * 50 + kp] : 0.f;
    }
    for (int i = tid; i < 21632; i += TPB) {
        int kg = i / 1664, r = i % 1664;
        int j = r / 64, g = (r % 64) / 16, k_id = (r % 16) / 4, c = r % 4;
        int k = kg * 4 + k_id, kp = j * 4 + c;
        float v = 0.f;
        if (k < 50) {
            if (kp < 50)       v = W_ih1[(g * 50 + k) * 50 + kp];
            else if (kp < 100) v = W_hh1[(g * 50 + k) * 50 + (kp - 50)];
        }
        W2n[i] = v;
    }
    for (int i = tid; i < 208; i += TPB) {
        int kg = i / 16, k_id = (i % 16) / 4, g = i % 4;
        int k = kg * 4 + k_id;
        wx1n[i] = (k < 50) ? W_ih0[g * 50 + k] : 0.f;
        bs1n[i] = (k < 50) ? (b_ih0[g * 50 + k] + b_hh0[g * 50 + k]) : 0.f;
        bs2n[i] = (k < 50) ? (b_ih1[g * 50 + k] + b_hh1[g * 50 + k]) : 0.f;
    }
    for (int i = tid; i < 3216; i += TPB) hcT[i] = 0.f;

    const int kg   = tid >> 5;        // warp = k-group 0..12
    const int lane = tid & 31;
    const int k_id = lane & 3;
    const int b_id = lane >> 2;       // 0..7
    const int k    = kg * 4 + k_id;
    const bool kvalid = (k < 50);
    const int bbase = blockIdx.x * BT;

    // per-lane weight chunk base: ulonglong2 index = ((kg*13 + j)*4 + g)*4 + k_id
    const ulonglong2* W1p = (const ulonglong2*)W1n + kg * 208 + k_id;
    const ulonglong2* W2p = (const ulonglong2*)W2n + kg * 416 + k_id;
    const ulonglong2* hp0 = (const ulonglong2*)(hcT + (0 * 8 + b_id) * 100);
    const ulonglong2* hp1 = (const ulonglong2*)(hcT + (1 * 8 + b_id) * 100);
    const ulonglong2* hp2 = (const ulonglong2*)(hcT + (2 * 8 + b_id) * 100);
    const ulonglong2* hp3 = (const ulonglong2*)(hcT + (3 * 8 + b_id) * 100);

    __syncthreads();

    // t-invariant per-lane params
    const float4 wx4 = *(const float4*)(wx1n + (kg * 4 + k_id) * 4);
    const float4 b14 = *(const float4*)(bs1n + (kg * 4 + k_id) * 4);
    const float4 b24 = *(const float4*)(bs2n + (kg * 4 + k_id) * 4);

    float c1[4] = {0.f, 0.f, 0.f, 0.f};
    float c2[4] = {0.f, 0.f, 0.f, 0.f};
    float nh[4];

    for (int t = 0; t < T; t++) {
        // x for the 4 batch-groups (consumed after the L1 j-loop)
        const float* xrow = g_xT + (size_t)t * B + bbase + b_id;
        float xv0 = xrow[0], xv1 = xrow[8], xv2 = xrow[16], xv3 = xrow[24];

        // ================= layer 1 (reads h1 old: rows 0..51) =================
        ull a[4][4];   // [bg][gate], packed pairs over kp
#pragma unroll
        for (int bg = 0; bg < 4; bg++) {
            a[bg][0] = pack2(b14.x, 0.f); a[bg][1] = pack2(b14.y, 0.f);
            a[bg][2] = pack2(b14.z, 0.f); a[bg][3] = pack2(b14.w, 0.f);
        }
#pragma unroll
        for (int j = 0; j < 13; j++) {
            ulonglong2 w0 = W1p[(j * 4 + 0) * 4];
            ulonglong2 w1 = W1p[(j * 4 + 1) * 4];
            ulonglong2 w2 = W1p[(j * 4 + 2) * 4];
            ulonglong2 w3 = W1p[(j * 4 + 3) * 4];
            ulonglong2 h0 = hp0[j], h1 = hp1[j], h2 = hp2[j], h3 = hp3[j];
            ffma2(a[0][0], w0.x, h0.x); ffma2(a[0][0], w0.y, h0.y);
            ffma2(a[0][1], w1.x, h0.x); ffma2(a[0][1], w1.y, h0.y);
            ffma2(a[0][2], w2.x, h0.x); ffma2(a[0][2], w2.y, h0.y);
            ffma2(a[0][3], w3.x, h0.x); ffma2(a[0][3], w3.y, h0.y);
            ffma2(a[1][0], w0.x, h1.x); ffma2(a[1][0], w0.y, h1.y);
            ffma2(a[1][1], w1.x, h1.x); ffma2(a[1][1], w1.y, h1.y);
            ffma2(a[1][2], w2.x, h1.x); ffma2(a[1][2], w2.y, h1.y);
            ffma2(a[1][3], w3.x, h1.x); ffma2(a[1][3], w3.y, h1.y);
            ffma2(a[2][0], w0.x, h2.x); ffma2(a[2][0], w0.y, h2.y);
            ffma2(a[2][1], w1.x, h2.x); ffma2(a[2][1], w1.y, h2.y);
            ffma2(a[2][2], w2.x, h2.x); ffma2(a[2][2], w2.y, h2.y);
            ffma2(a[2][3], w3.x, h2.x); ffma2(a[2][3], w3.y, h2.y);
            ffma2(a[3][0], w0.x, h3.x); ffma2(a[3][0], w0.y, h3.y);
            ffma2(a[3][1], w1.x, h3.x); ffma2(a[3][1], w1.y, h3.y);
            ffma2(a[3][2], w2.x, h3.x); ffma2(a[3][2], w2.y, h3.y);
            ffma2(a[3][3], w3.x, h3.x); ffma2(a[3][3], w3.y, h3.y);
        }
        {
            float xv[4] = {xv0, xv1, xv2, xv3};
#pragma unroll
            for (int bg = 0; bg < 4; bg++) {
                float2 vi = unpack2(a[bg][0]), vf = unpack2(a[bg][1]);
                float2 vg = unpack2(a[bg][2]), vo = unpack2(a[bg][3]);
                float gi = fmaf(xv[bg], wx4.x, vi.x + vi.y);
                float gf = fmaf(xv[bg], wx4.y, vf.x + vf.y);
                float gg = fmaf(xv[bg], wx4.z, vg.x + vg.y);
                float go = fmaf(xv[bg], wx4.w, vo.x + vo.y);
                c1[bg] = sigf(gf) * c1[bg] + sigf(gi) * tanf_(gg);
                nh[bg] = sigf(go) * tanf_(c1[bg]);
            }
        }

        __syncthreads();   // all reads of old h1 done
        if (kvalid) {
#pragma unroll
            for (int bg = 0; bg < 4; bg++)
                hcT[(bg * 8 + b_id) * 100 + k] = nh[bg];
        }
        __syncthreads();   // new h1 visible

        // ================= layer 2 (reads rows 0..103; 100..103 * zero w) =====
#pragma unroll
        for (int bg = 0; bg < 4; bg++) {
            a[bg][0] = pack2(b24.x, 0.f); a[bg][1] = pack2(b24.y, 0.f);
            a[bg][2] = pack2(b24.z, 0.f); a[bg][3] = pack2(b24.w, 0.f);
        }
#pragma unroll 13
        for (int j = 0; j < 26; j++) {
            ulonglong2 w0 = W2p[(j * 4 + 0) * 4];
            ulonglong2 w1 = W2p[(j * 4 + 1) * 4];
            ulonglong2 w2 = W2p[(j * 4 + 2) * 4];
            ulonglong2 w3 = W2p[(j * 4 + 3) * 4];
            ulonglong2 h0 = hp0[j], h1 = hp1[j], h2 = hp2[j], h3 = hp3[j];
            ffma2(a[0][0], w0.x, h0.x); ffma2(a[0][0], w0.y, h0.y);
            ffma2(a[0][1], w1.x, h0.x); ffma2(a[0][1], w1.y, h0.y);
            ffma2(a[0][2], w2.x, h0.x); ffma2(a[0][2], w2.y, h0.y);
            ffma2(a[0][3], w3.x, h0.x); ffma2(a[0][3], w3.y, h0.y);
            ffma2(a[1][0], w0.x, h1.x); ffma2(a[1][0], w0.y, h1.y);
            ffma2(a[1][1], w1.x, h1.x); ffma2(a[1][1], w1.y, h1.y);
            ffma2(a[1][2], w2.x, h1.x); ffma2(a[1][2], w2.y, h1.y);
            ffma2(a[1][3], w3.x, h1.x); ffma2(a[1][3], w3.y, h1.y);
            ffma2(a[2][0], w0.x, h2.x); ffma2(a[2][0], w0.y, h2.y);
            ffma2(a[2][1], w1.x, h2.x); ffma2(a[2][1], w1.y, h2.y);
            ffma2(a[2][2], w2.x, h2.x); ffma2(a[2][2], w2.y, h2.y);
            ffma2(a[2][3], w3.x, h2.x); ffma2(a[2][3], w3.y, h2.y);
            ffma2(a[3][0], w0.x, h3.x); ffma2(a[3][0], w0.y, h3.y);
            ffma2(a[3][1], w1.x, h3.x); ffma2(a[3][1], w1.y, h3.y);
            ffma2(a[3][2], w2.x, h3.x); ffma2(a[3][2], w2.y, h3.y);
            ffma2(a[3][3], w3.x, h3.x); ffma2(a[3][3], w3.y, h3.y);
        }
#pragma unroll
        for (int bg = 0; bg < 4; bg++) {
            float2 vi = unpack2(a[bg][0]), vf = unpack2(a[bg][1]);
            float2 vg = unpack2(a[bg][2]), vo = unpack2(a[bg][3]);
            float gi = vi.x + vi.y, gf = vf.x + vf.y;
            float gg = vg.x + vg.y, go = vo.x + vo.y;
            c2[bg] = sigf(gf) * c2[bg] + sigf(gi) * tanf_(gg);
            nh[bg] = sigf(go) * tanf_(c2[bg]);
        }

        __syncthreads();   // all reads of old h2 done
        if (kvalid) {
#pragma unroll
            for (int bg = 0; bg < 4; bg++)
                hcT[(bg * 8 + b_id) * 100 + 50 + k] = nh[bg];
        }
        // next step's L1 reads rows 0..51; rows 50,51 race benignly (zero weights).
    }

    __syncthreads();
    // ---- final FC ----
    if (tid < BT) {
        float acc = b_fc[0];
#pragma unroll 10
        for (int kk = 0; kk < 50; kk++)
            acc = fmaf(hcT[tid * 100 + 50 + kk], W_fc[kk], acc);
        out[bbase + tid] = acc;
    }
}

extern "C" void kernel_launch(void* const* d_in, const int* in_sizes, int n_in,
                              void* d_out, int out_size) {
    const float* x     = (const float*)d_in[0];
    const float* W_ih0 = (const float*)d_in[1];
    const float* W_hh0 = (const float*)d_in[2];
    const float* b_ih0 = (const float*)d_in[3];
    const float* b_hh0 = (const float*)d_in[4];
    const float* W_ih1 = (const float*)d_in[5];
    const float* W_hh1 = (const float*)d_in[6];
    const float* b_ih1 = (const float*)d_in[7];
    const float* b_hh1 = (const float*)d_in[8];
    const float* W_fc  = (const float*)d_in[9];
    const float* b_fc  = (const float*)d_in[10];
    float* out = (float*)d_out;

    int B = out_size;                 // 4096
    int T = in_sizes[0] / B;          // 512

    dim3 tb(32, 8), tg(T / 32, B / 32);
    transpose_kernel<<<tg, tb>>>(x, B, T);

    cudaFuncSetAttribute(lstm_kernel, cudaFuncAttributeMaxDynamicSharedMemorySize,
                         SME_TOT * sizeof(float));
    lstm_kernel<<<B / BT, TPB, SME_TOT * sizeof(float)>>>(
        W_ih0, W_hh0, b_ih0, b_hh0, W_ih1, W_hh1, b_ih1, b_hh1,
        W_fc, b_fc, out, B, T);
}